// round 6
// baseline (speedup 1.0000x reference)
#include <cuda_runtime.h>
#include <cuda_bf16.h>
#include <cstdint>

#define KN      100000
#define KE      1600000
#define KIN     256
#define KED     64
#define KH      4
#define KC      32
#define KHC     128
#define KNB     ((KE + 31) / 32)

#define FULLM 0xFFFFFFFFu

// ---------------- scratch (static device globals; no allocation) ----------------
__device__ float4 g_xproj[KN * 32];        // [N][128]  (51.2 MB)
__device__ float4 g_asrc[KN];
__device__ float4 g_adst[KN];
__device__ float  g_W2[KED * KH];          // [64][4]
__device__ float  g_WS[KH * KIN];          // [h][k]
__device__ float  g_WD[KH * KIN];          // [h][k]
__device__ float  g_loopsum[KH];
__device__ int    g_deg[KN];
__device__ int    g_off[KN + 1];
__device__ int    g_cursor[KN];
__device__ int    g_ssrc[KE];
__device__ float4 g_salpha[KE];            // (25.6 MB)
__device__ float4 g_part[KNB];

// ---------------- reset ----------------
__global__ void k_reset(int n) {
    int i = blockIdx.x * blockDim.x + threadIdx.x;
    if (i < n) g_deg[i] = 0;
    if (i < KH) g_loopsum[i] = 0.f;
}

// ---------------- prep: W2, WS, WD ----------------
__global__ void k_prep(const float* __restrict__ W,
                       const float* __restrict__ W_edge,
                       const float* __restrict__ att_edge,
                       const float* __restrict__ att_src,
                       const float* __restrict__ att_dst) {
    int t = threadIdx.x;                 // 256
    if (blockIdx.x == 0) {
        // W2[d][h] = sum_c W_edge[d, h*32+c] * att_edge[h, c]
        int d = t >> 2, h = t & 3;
        float s = 0.f;
        #pragma unroll 8
        for (int c = 0; c < KC; c++)
            s += W_edge[d * KHC + h * KC + c] * att_edge[h * KC + c];
        g_W2[d * KH + h] = s;
    } else {
        // WS[h][k] = sum_c W[k, h*32+c] * att_src[h,c]; same for WD
        const float* wr = W + (size_t)t * KHC;
        #pragma unroll
        for (int h = 0; h < KH; h++) {
            float s = 0.f, d = 0.f;
            #pragma unroll 8
            for (int c = 0; c < KC; c++) {
                float wv = wr[h * KC + c];
                s += wv * att_src[h * KC + c];
                d += wv * att_dst[h * KC + c];
            }
            g_WS[h * KIN + t] = s;
            g_WD[h * KIN + t] = d;
        }
    }
}

// ---------------- a_src/a_dst GEMV: warp per node, direct from x ----------------
__global__ __launch_bounds__(256) void k_av(const float* __restrict__ x, int n) {
    __shared__ float WS[KH * KIN];
    __shared__ float WD[KH * KIN];
    int tid = threadIdx.x;
    for (int i = tid; i < KH * KIN; i += 256) { WS[i] = g_WS[i]; WD[i] = g_WD[i]; }
    __syncthreads();
    int warp = (blockIdx.x * blockDim.x + tid) >> 5;
    int lane = tid & 31;
    if (warp >= n) return;
    const float* xr = x + (size_t)warp * KIN;
    float as[4] = {0.f, 0.f, 0.f, 0.f}, ad[4] = {0.f, 0.f, 0.f, 0.f};
    #pragma unroll
    for (int j = 0; j < 8; j++) {
        int k = j * 32 + lane;          // conflict-free smem, coalesced gmem
        float xv = xr[k];
        #pragma unroll
        for (int h = 0; h < KH; h++) {
            as[h] += xv * WS[h * KIN + k];
            ad[h] += xv * WD[h * KIN + k];
        }
    }
    #pragma unroll
    for (int m = 1; m <= 16; m <<= 1) {
        #pragma unroll
        for (int h = 0; h < KH; h++) {
            as[h] += __shfl_xor_sync(FULLM, as[h], m);
            ad[h] += __shfl_xor_sync(FULLM, ad[h], m);
        }
    }
    if (lane == 0) {
        g_asrc[warp] = make_float4(as[0], as[1], as[2], as[3]);
        g_adst[warp] = make_float4(ad[0], ad[1], ad[2], ad[3]);
    }
}

// ---------------- GEMM: x_proj = x[N,256] @ W[256,128]  (round-2 proven fp32) ----------------
__global__ __launch_bounds__(256) void k_gemm(const float* __restrict__ x,
                                              const float* __restrict__ W, int n) {
    __shared__ float Xs[16][128];
    __shared__ float Ws[16][128];
    int tid = threadIdx.x;
    int bm = blockIdx.x * 128;
    int tx = tid & 15;
    int ty = tid >> 4;

    float acc[8][8];
    #pragma unroll
    for (int i = 0; i < 8; i++)
        #pragma unroll
        for (int j = 0; j < 8; j++) acc[i][j] = 0.f;

    int xr = tid >> 2;
    int xk = (tid & 3) << 2;
    int wk = tid >> 5;
    int wn = (tid & 31) << 2;

    for (int kb = 0; kb < KIN; kb += 16) {
        #pragma unroll
        for (int h = 0; h < 2; h++) {
            int m = xr + h * 64;
            int gm = bm + m;
            float4 v = make_float4(0.f, 0.f, 0.f, 0.f);
            if (gm < n) v = *(const float4*)(x + (size_t)gm * KIN + kb + xk);
            Xs[xk + 0][m] = v.x;
            Xs[xk + 1][m] = v.y;
            Xs[xk + 2][m] = v.z;
            Xs[xk + 3][m] = v.w;
        }
        #pragma unroll
        for (int h = 0; h < 2; h++) {
            int k = wk + h * 8;
            *(float4*)&Ws[k][wn] = *(const float4*)(W + (size_t)(kb + k) * KHC + wn);
        }
        __syncthreads();
        #pragma unroll
        for (int k = 0; k < 16; k++) {
            float4 a0 = *(const float4*)&Xs[k][ty * 8];
            float4 a1 = *(const float4*)&Xs[k][ty * 8 + 4];
            float4 b0 = *(const float4*)&Ws[k][tx * 4];
            float4 b1 = *(const float4*)&Ws[k][tx * 4 + 64];
            float av[8] = {a0.x, a0.y, a0.z, a0.w, a1.x, a1.y, a1.z, a1.w};
            float bv[8] = {b0.x, b0.y, b0.z, b0.w, b1.x, b1.y, b1.z, b1.w};
            #pragma unroll
            for (int i = 0; i < 8; i++)
                #pragma unroll
                for (int j = 0; j < 8; j++)
                    acc[i][j] += av[i] * bv[j];
        }
        __syncthreads();
    }
    #pragma unroll
    for (int i = 0; i < 8; i++) {
        int gm = bm + ty * 8 + i;
        if (gm < n) {
            g_xproj[(size_t)gm * 32 + tx] =
                make_float4(acc[i][0], acc[i][1], acc[i][2], acc[i][3]);
            g_xproj[(size_t)gm * 32 + 16 + tx] =
                make_float4(acc[i][4], acc[i][5], acc[i][6], acc[i][7]);
        }
    }
}

// ---------------- histogram of dst ----------------
__global__ void k_hist(const int* __restrict__ edge_index, int E) {
    int e = blockIdx.x * blockDim.x + threadIdx.x;
    if (e < E) atomicAdd(&g_deg[edge_index[E + e]], 1);
}

// ---------------- single-block scan ----------------
__global__ void k_scan(int n) {
    __shared__ int s[1024];
    int t = threadIdx.x;
    int chunk = (n + 1023) / 1024;
    int start = t * chunk;
    int sum = 0;
    for (int j = 0; j < chunk; j++) {
        int i = start + j;
        if (i < n) sum += g_deg[i];
    }
    s[t] = sum;
    __syncthreads();
    for (int o = 1; o < 1024; o <<= 1) {
        int v = (t >= o) ? s[t - o] : 0;
        __syncthreads();
        s[t] += v;
        __syncthreads();
    }
    int run = s[t] - sum;
    for (int j = 0; j < chunk; j++) {
        int i = start + j;
        if (i < n) {
            g_off[i] = run;
            g_cursor[i] = run;
            run += g_deg[i];
        }
    }
    if (t == 1023) g_off[n] = s[1023];
}

// ---------------- scatter: 8 lanes per edge (4 edges/warp) ----------------
__global__ __launch_bounds__(256) void k_scatter(const int* __restrict__ edge_index,
                                                 const float* __restrict__ edge_attr, int E) {
    __shared__ float Ws2[KED * KH];
    __shared__ float bp[KH];
    int tid = threadIdx.x;
    Ws2[tid] = g_W2[tid];
    if (tid < KH) bp[tid] = 0.f;
    __syncthreads();

    int lane = tid & 31;
    int wid = tid >> 5;
    int g8 = lane >> 3, l8 = lane & 7;
    int e = blockIdx.x * 32 + wid * 4 + g8;

    float p0 = 0.f, p1 = 0.f, p2 = 0.f, p3 = 0.f;
    if (e < E) {
        const float* ea = edge_attr + (size_t)e * KED + l8 * 8;
        float4 v0 = *(const float4*)ea;
        float4 v1 = *(const float4*)(ea + 4);
        float av[8] = {v0.x, v0.y, v0.z, v0.w, v1.x, v1.y, v1.z, v1.w};
        int db = l8 * 8;
        #pragma unroll
        for (int j = 0; j < 8; j++) {
            const float* w = &Ws2[(db + j) * 4];
            p0 += av[j] * w[0];
            p1 += av[j] * w[1];
            p2 += av[j] * w[2];
            p3 += av[j] * w[3];
        }
    }
    #pragma unroll
    for (int m = 1; m <= 4; m <<= 1) {
        p0 += __shfl_xor_sync(FULLM, p0, m);
        p1 += __shfl_xor_sync(FULLM, p1, m);
        p2 += __shfl_xor_sync(FULLM, p2, m);
        p3 += __shfl_xor_sync(FULLM, p3, m);
    }
    if (l8 == 0 && e < E) {
        atomicAdd(&bp[0], p0);
        atomicAdd(&bp[1], p1);
        atomicAdd(&bp[2], p2);
        atomicAdd(&bp[3], p3);
        int src = edge_index[e];
        int dst = edge_index[E + e];
        float4 as = g_asrc[src];
        int pos = atomicAdd(&g_cursor[dst], 1);
        g_ssrc[pos] = src;
        g_salpha[pos] = make_float4(as.x + p0, as.y + p1, as.z + p2, as.w + p3);
    }
    __syncthreads();
    if (tid < KH) ((float*)&g_part[blockIdx.x])[tid] = bp[tid];
}

// ---------------- reduce per-block p-sums ----------------
__global__ void k_psum(int nb) {
    int tid = blockIdx.x * blockDim.x + threadIdx.x;
    int stride = gridDim.x * blockDim.x;
    float4 s = make_float4(0.f, 0.f, 0.f, 0.f);
    for (int j = tid; j < nb; j += stride) {
        float4 v = g_part[j];
        s.x += v.x; s.y += v.y; s.z += v.z; s.w += v.w;
    }
    #pragma unroll
    for (int m = 16; m >= 1; m >>= 1) {
        s.x += __shfl_xor_sync(FULLM, s.x, m);
        s.y += __shfl_xor_sync(FULLM, s.y, m);
        s.z += __shfl_xor_sync(FULLM, s.z, m);
        s.w += __shfl_xor_sync(FULLM, s.w, m);
    }
    __shared__ float4 ws[8];
    int warp = threadIdx.x >> 5;
    int lane = threadIdx.x & 31;
    if (lane == 0) ws[warp] = s;
    __syncthreads();
    if (warp == 0) {
        float4 v = (lane < 8) ? ws[lane] : make_float4(0.f, 0.f, 0.f, 0.f);
        #pragma unroll
        for (int m = 4; m >= 1; m >>= 1) {
            v.x += __shfl_xor_sync(FULLM, v.x, m);
            v.y += __shfl_xor_sync(FULLM, v.y, m);
            v.z += __shfl_xor_sync(FULLM, v.z, m);
            v.w += __shfl_xor_sync(FULLM, v.w, m);
        }
        if (lane == 0) {
            atomicAdd(&g_loopsum[0], v.x);
            atomicAdd(&g_loopsum[1], v.y);
            atomicAdd(&g_loopsum[2], v.z);
            atomicAdd(&g_loopsum[3], v.w);
        }
    }
}

// ---------------- aggregation ----------------
__global__ __launch_bounds__(256) void k_agg(const float* __restrict__ bias,
                                             float* __restrict__ out, int n, float invE) {
    int i = (blockIdx.x * blockDim.x + threadIdx.x) >> 5;
    int lane = threadIdx.x & 31;
    if (i >= n) return;

    int hl = lane >> 3;
    int sub = lane & 3;

    float adst_s = ((const float*)&g_adst[i])[sub];
    float asrc_s = ((const float*)&g_asrc[i])[sub];
    float lae_s  = g_loopsum[sub] * invE;
    float4 xpi = g_xproj[(size_t)i * 32 + lane];

    float4 acc = make_float4(0.f, 0.f, 0.f, 0.f);
    float dsum = 0.f;

    float vs = asrc_s + adst_s + lae_s;
    vs = vs > 0.f ? vs : 0.2f * vs;
    float ws = __expf(vs);
    if (lane < 4) dsum += ws;
    {
        float w = __shfl_sync(FULLM, ws, hl);
        acc.x += w * xpi.x; acc.y += w * xpi.y; acc.z += w * xpi.z; acc.w += w * xpi.w;
    }

    int beg = g_off[i], end = g_off[i + 1];
    const float* salpha_f = (const float*)g_salpha;
    for (int base = beg; base < end; base += 8) {
        int myedge = base + (lane >> 2);
        float w = 0.f;
        if (myedge < end) {
            float a = salpha_f[(size_t)base * 4 + lane] + adst_s;
            a = a > 0.f ? a : 0.2f * a;
            w = __expf(a);
        }
        dsum += w;
        int sv = i;
        if (lane < 8 && base + lane < end) sv = g_ssrc[base + lane];
        #pragma unroll
        for (int k = 0; k < 8; k++) {
            int s = __shfl_sync(FULLM, sv, k);
            float we = __shfl_sync(FULLM, w, k * 4 + hl);
            float4 xp = g_xproj[(size_t)s * 32 + lane];
            acc.x += we * xp.x; acc.y += we * xp.y;
            acc.z += we * xp.z; acc.w += we * xp.w;
        }
    }
    #pragma unroll
    for (int m = 4; m <= 16; m <<= 1) dsum += __shfl_xor_sync(FULLM, dsum, m);
    float denom = __shfl_sync(FULLM, dsum, hl);
    float inv = 1.0f / denom;
    float4 b4 = *(const float4*)(bias + lane * 4);
    float4 o;
    o.x = acc.x * inv + b4.x;
    o.y = acc.y * inv + b4.y;
    o.z = acc.z * inv + b4.z;
    o.w = acc.w * inv + b4.w;
    *(float4*)(out + (size_t)i * KHC + lane * 4) = o;
}

// ---------------- launch: fork GEMM chain and edge chain onto two streams ----------------
extern "C" void kernel_launch(void* const* d_in, const int* in_sizes, int n_in,
                              void* d_out, int out_size) {
    const float* x         = (const float*)d_in[0];
    const int*   edge_idx  = (const int*)d_in[1];
    const float* edge_attr = (const float*)d_in[2];
    const float* W         = (const float*)d_in[3];
    const float* att_src   = (const float*)d_in[4];
    const float* att_dst   = (const float*)d_in[5];
    const float* W_edge    = (const float*)d_in[6];
    const float* att_edge  = (const float*)d_in[7];
    const float* bias      = (const float*)d_in[8];
    float* out = (float*)d_out;

    int n = in_sizes[0] / KIN;       // 100000
    int E = in_sizes[1] / 2;         // 1600000
    int nb = (E + 31) / 32;

    static cudaStream_t sA = nullptr, sB = nullptr;
    static cudaEvent_t e0 = nullptr, eA = nullptr, eB = nullptr;
    if (!sA) {
        cudaStreamCreateWithFlags(&sA, cudaStreamNonBlocking);
        cudaStreamCreateWithFlags(&sB, cudaStreamNonBlocking);
        cudaEventCreateWithFlags(&e0, cudaEventDisableTiming);
        cudaEventCreateWithFlags(&eA, cudaEventDisableTiming);
        cudaEventCreateWithFlags(&eB, cudaEventDisableTiming);
    }

    // common prologue on the (captured) legacy stream
    k_reset<<<(n + 255) / 256, 256>>>(n);
    k_prep<<<2, 256>>>(W, W_edge, att_edge, att_src, att_dst);
    cudaEventRecord(e0, 0);
    cudaStreamWaitEvent(sA, e0, 0);
    cudaStreamWaitEvent(sB, e0, 0);

    // chain A: dense GEMM (FFMA-bound)
    k_gemm<<<(n + 127) / 128, 256, 0, sA>>>(x, W, n);

    // chain B: attention logits + CSR build (memory-bound)
    k_av<<<(n + 7) / 8, 256, 0, sB>>>(x, n);
    k_hist<<<(E + 255) / 256, 256, 0, sB>>>(edge_idx, E);
    k_scan<<<1, 1024, 0, sB>>>(n);
    k_scatter<<<nb, 256, 0, sB>>>(edge_idx, edge_attr, E);
    k_psum<<<64, 256, 0, sB>>>(nb);

    // join and aggregate
    cudaEventRecord(eA, sA);
    cudaEventRecord(eB, sB);
    cudaStreamWaitEvent(0, eA, 0);
    cudaStreamWaitEvent(0, eB, 0);
    k_agg<<<(n + 7) / 8, 256>>>(bias, out, n, 1.0f / (float)E);
}

// round 7
// speedup vs baseline: 1.0261x; 1.0261x over previous
#include <cuda_runtime.h>
#include <cuda_bf16.h>
#include <cstdint>

#define KN      100000
#define KE      1600000
#define KIN     256
#define KED     64
#define KH      4
#define KC      32
#define KHC     128
#define KNB     ((KE + 31) / 32)

#define FULLM 0xFFFFFFFFu

// ---------------- scratch (static device globals; no allocation) ----------------
__device__ float4 g_xproj[KN * 32];        // [N][128]  (51.2 MB)
__device__ float4 g_asrc[KN];
__device__ float4 g_adst[KN];
__device__ float  g_W2[KED * KH];          // [64][4]
__device__ float  g_loopsum[KH];
__device__ int    g_deg[KN];
__device__ int    g_off[KN + 1];
__device__ int    g_cursor[KN];
__device__ int    g_ssrc[KE];
__device__ float4 g_salpha[KE];            // (25.6 MB)
__device__ float4 g_part[KNB];

// ---------------- packed f32x2 helpers ----------------
__device__ __forceinline__ void fma2(unsigned long long& acc, unsigned long long a,
                                     unsigned long long b) {
    asm("fma.rn.f32x2 %0, %1, %2, %0;" : "+l"(acc) : "l"(a), "l"(b));
}
__device__ __forceinline__ unsigned long long dup2(float v) {
    unsigned long long r;
    asm("mov.b64 %0, {%1, %1};" : "=l"(r) : "r"(__float_as_uint(v)));
    return r;
}

// ---------------- reset ----------------
__global__ void k_reset(int n) {
    int i = blockIdx.x * blockDim.x + threadIdx.x;
    if (i < n) g_deg[i] = 0;
    if (i < KH) g_loopsum[i] = 0.f;
}

// ---------------- W2[d][h] = sum_c W_edge[d, h*32+c] * att_edge[h, c] ----------------
__global__ void k_w2(const float* __restrict__ W_edge, const float* __restrict__ att_edge) {
    int t = threadIdx.x;                 // 256 threads
    int d = t >> 2, h = t & 3;
    float s = 0.f;
    #pragma unroll 8
    for (int c = 0; c < KC; c++)
        s += W_edge[d * KHC + h * KC + c] * att_edge[h * KC + c];
    g_W2[d * KH + h] = s;
}

// ---------------- GEMM: x_proj = x[N,256] @ W[256,128], packed f32x2 FMA ----------------
// 256 threads, tile 128(M) x 128(N), K-chunks of 16, 8x8 microtile as 8x4 packed pairs.
__global__ __launch_bounds__(256) void k_gemm(const float* __restrict__ x,
                                              const float* __restrict__ W, int n) {
    __shared__ float Xs[16][128];
    __shared__ float Ws[16][128];
    int tid = threadIdx.x;
    int bm = blockIdx.x * 128;
    int tx = tid & 15;           // 0..15
    int ty = tid >> 4;           // 0..15

    unsigned long long acc[8][4];
    #pragma unroll
    for (int i = 0; i < 8; i++)
        #pragma unroll
        for (int j = 0; j < 4; j++) acc[i][j] = 0ULL;

    int xr = tid >> 2;
    int xk = (tid & 3) << 2;
    int wk = tid >> 5;
    int wn = (tid & 31) << 2;

    for (int kb = 0; kb < KIN; kb += 16) {
        #pragma unroll
        for (int h = 0; h < 2; h++) {
            int m = xr + h * 64;
            int gm = bm + m;
            float4 v = make_float4(0.f, 0.f, 0.f, 0.f);
            if (gm < n) v = *(const float4*)(x + (size_t)gm * KIN + kb + xk);
            Xs[xk + 0][m] = v.x;
            Xs[xk + 1][m] = v.y;
            Xs[xk + 2][m] = v.z;
            Xs[xk + 3][m] = v.w;
        }
        #pragma unroll
        for (int h = 0; h < 2; h++) {
            int k = wk + h * 8;
            *(float4*)&Ws[k][wn] = *(const float4*)(W + (size_t)(kb + k) * KHC + wn);
        }
        __syncthreads();
        #pragma unroll
        for (int k = 0; k < 16; k++) {
            float4 a0 = *(const float4*)&Xs[k][ty * 8];
            float4 a1 = *(const float4*)&Xs[k][ty * 8 + 4];
            // B pairs: (tx*4+0,1) (tx*4+2,3) (64+tx*4+0,1) (64+tx*4+2,3)
            ulonglong2 b0 = *(const ulonglong2*)&Ws[k][tx * 4];
            ulonglong2 b1 = *(const ulonglong2*)&Ws[k][tx * 4 + 64];
            float av[8] = {a0.x, a0.y, a0.z, a0.w, a1.x, a1.y, a1.z, a1.w};
            #pragma unroll
            for (int i = 0; i < 8; i++) {
                unsigned long long a2 = dup2(av[i]);
                fma2(acc[i][0], a2, b0.x);
                fma2(acc[i][1], a2, b0.y);
                fma2(acc[i][2], a2, b1.x);
                fma2(acc[i][3], a2, b1.y);
            }
        }
        __syncthreads();
    }
    #pragma unroll
    for (int i = 0; i < 8; i++) {
        int gm = bm + ty * 8 + i;
        if (gm < n) {
            float2 p0 = *(float2*)&acc[i][0];
            float2 p1 = *(float2*)&acc[i][1];
            float2 p2 = *(float2*)&acc[i][2];
            float2 p3 = *(float2*)&acc[i][3];
            g_xproj[(size_t)gm * 32 + tx] = make_float4(p0.x, p0.y, p1.x, p1.y);
            g_xproj[(size_t)gm * 32 + 16 + tx] = make_float4(p2.x, p2.y, p3.x, p3.y);
        }
    }
}

// ---------------- a_src / a_dst: warp per node (reads L2-resident g_xproj) ----------------
__global__ void k_attn(const float* __restrict__ att_src,
                       const float* __restrict__ att_dst, int n) {
    int warp = (blockIdx.x * blockDim.x + threadIdx.x) >> 5;
    int lane = threadIdx.x & 31;
    if (warp >= n) return;
    float4 xp = g_xproj[(size_t)warp * 32 + lane];
    float4 as = *(const float4*)(att_src + lane * 4);
    float4 ad = *(const float4*)(att_dst + lane * 4);
    float ds = xp.x * as.x + xp.y * as.y + xp.z * as.z + xp.w * as.w;
    float dd = xp.x * ad.x + xp.y * ad.y + xp.z * ad.z + xp.w * ad.w;
    #pragma unroll
    for (int m = 1; m <= 4; m <<= 1) {
        ds += __shfl_xor_sync(FULLM, ds, m);
        dd += __shfl_xor_sync(FULLM, dd, m);
    }
    if ((lane & 7) == 0) {
        int h = lane >> 3;
        ((float*)&g_asrc[warp])[h] = ds;
        ((float*)&g_adst[warp])[h] = dd;
    }
}

// ---------------- histogram of dst ----------------
__global__ void k_hist(const int* __restrict__ edge_index, int E) {
    int e = blockIdx.x * blockDim.x + threadIdx.x;
    if (e < E) atomicAdd(&g_deg[edge_index[E + e]], 1);
}

// ---------------- single-block scan ----------------
__global__ void k_scan(int n) {
    __shared__ int s[1024];
    int t = threadIdx.x;
    int chunk = (n + 1023) / 1024;
    int start = t * chunk;
    int sum = 0;
    for (int j = 0; j < chunk; j++) {
        int i = start + j;
        if (i < n) sum += g_deg[i];
    }
    s[t] = sum;
    __syncthreads();
    for (int o = 1; o < 1024; o <<= 1) {
        int v = (t >= o) ? s[t - o] : 0;
        __syncthreads();
        s[t] += v;
        __syncthreads();
    }
    int run = s[t] - sum;
    for (int j = 0; j < chunk; j++) {
        int i = start + j;
        if (i < n) {
            g_off[i] = run;
            g_cursor[i] = run;
            run += g_deg[i];
        }
    }
    if (t == 1023) g_off[n] = s[1023];
}

// ---------------- scatter: 8 lanes per edge (4 edges/warp) ----------------
__global__ __launch_bounds__(256) void k_scatter(const int* __restrict__ edge_index,
                                                 const float* __restrict__ edge_attr, int E) {
    __shared__ float Ws2[KED * KH];
    __shared__ float bp[KH];
    int tid = threadIdx.x;
    Ws2[tid] = g_W2[tid];
    if (tid < KH) bp[tid] = 0.f;
    __syncthreads();

    int lane = tid & 31;
    int wid = tid >> 5;
    int g8 = lane >> 3, l8 = lane & 7;
    int e = blockIdx.x * 32 + wid * 4 + g8;

    float p0 = 0.f, p1 = 0.f, p2 = 0.f, p3 = 0.f;
    if (e < E) {
        const float* ea = edge_attr + (size_t)e * KED + l8 * 8;
        float4 v0 = *(const float4*)ea;
        float4 v1 = *(const float4*)(ea + 4);
        float av[8] = {v0.x, v0.y, v0.z, v0.w, v1.x, v1.y, v1.z, v1.w};
        int db = l8 * 8;
        #pragma unroll
        for (int j = 0; j < 8; j++) {
            const float* w = &Ws2[(db + j) * 4];
            p0 += av[j] * w[0];
            p1 += av[j] * w[1];
            p2 += av[j] * w[2];
            p3 += av[j] * w[3];
        }
    }
    #pragma unroll
    for (int m = 1; m <= 4; m <<= 1) {
        p0 += __shfl_xor_sync(FULLM, p0, m);
        p1 += __shfl_xor_sync(FULLM, p1, m);
        p2 += __shfl_xor_sync(FULLM, p2, m);
        p3 += __shfl_xor_sync(FULLM, p3, m);
    }
    if (l8 == 0 && e < E) {
        atomicAdd(&bp[0], p0);
        atomicAdd(&bp[1], p1);
        atomicAdd(&bp[2], p2);
        atomicAdd(&bp[3], p3);
        int src = edge_index[e];
        int dst = edge_index[E + e];
        float4 as = g_asrc[src];
        int pos = atomicAdd(&g_cursor[dst], 1);
        g_ssrc[pos] = src;
        g_salpha[pos] = make_float4(as.x + p0, as.y + p1, as.z + p2, as.w + p3);
    }
    __syncthreads();
    if (tid < KH) ((float*)&g_part[blockIdx.x])[tid] = bp[tid];
}

// ---------------- reduce per-block p-sums ----------------
__global__ void k_psum(int nb) {
    int tid = blockIdx.x * blockDim.x + threadIdx.x;
    int stride = gridDim.x * blockDim.x;
    float4 s = make_float4(0.f, 0.f, 0.f, 0.f);
    for (int j = tid; j < nb; j += stride) {
        float4 v = g_part[j];
        s.x += v.x; s.y += v.y; s.z += v.z; s.w += v.w;
    }
    #pragma unroll
    for (int m = 16; m >= 1; m >>= 1) {
        s.x += __shfl_xor_sync(FULLM, s.x, m);
        s.y += __shfl_xor_sync(FULLM, s.y, m);
        s.z += __shfl_xor_sync(FULLM, s.z, m);
        s.w += __shfl_xor_sync(FULLM, s.w, m);
    }
    __shared__ float4 ws[8];
    int warp = threadIdx.x >> 5;
    int lane = threadIdx.x & 31;
    if (lane == 0) ws[warp] = s;
    __syncthreads();
    if (warp == 0) {
        float4 v = (lane < 8) ? ws[lane] : make_float4(0.f, 0.f, 0.f, 0.f);
        #pragma unroll
        for (int m = 4; m >= 1; m >>= 1) {
            v.x += __shfl_xor_sync(FULLM, v.x, m);
            v.y += __shfl_xor_sync(FULLM, v.y, m);
            v.z += __shfl_xor_sync(FULLM, v.z, m);
            v.w += __shfl_xor_sync(FULLM, v.w, m);
        }
        if (lane == 0) {
            atomicAdd(&g_loopsum[0], v.x);
            atomicAdd(&g_loopsum[1], v.y);
            atomicAdd(&g_loopsum[2], v.z);
            atomicAdd(&g_loopsum[3], v.w);
        }
    }
}

// ---------------- aggregation: warp per node, fused softmax + weighted sum ----------------
__global__ __launch_bounds__(256) void k_agg(const float* __restrict__ bias,
                                             float* __restrict__ out, int n, float invE) {
    int i = (blockIdx.x * blockDim.x + threadIdx.x) >> 5;
    int lane = threadIdx.x & 31;
    if (i >= n) return;

    int hl = lane >> 3;
    int sub = lane & 3;

    float adst_s = ((const float*)&g_adst[i])[sub];
    float asrc_s = ((const float*)&g_asrc[i])[sub];
    float lae_s  = g_loopsum[sub] * invE;
    float4 xpi = g_xproj[(size_t)i * 32 + lane];

    float4 acc = make_float4(0.f, 0.f, 0.f, 0.f);
    float dsum = 0.f;

    float vs = asrc_s + adst_s + lae_s;
    vs = vs > 0.f ? vs : 0.2f * vs;
    float ws = __expf(vs);
    if (lane < 4) dsum += ws;
    {
        float w = __shfl_sync(FULLM, ws, hl);
        acc.x += w * xpi.x; acc.y += w * xpi.y; acc.z += w * xpi.z; acc.w += w * xpi.w;
    }

    int beg = g_off[i], end = g_off[i + 1];
    const float* salpha_f = (const float*)g_salpha;
    for (int base = beg; base < end; base += 8) {
        int myedge = base + (lane >> 2);
        float w = 0.f;
        if (myedge < end) {
            float a = salpha_f[(size_t)base * 4 + lane] + adst_s;
            a = a > 0.f ? a : 0.2f * a;
            w = __expf(a);
        }
        dsum += w;
        int sv = i;
        if (lane < 8 && base + lane < end) sv = g_ssrc[base + lane];
        #pragma unroll
        for (int k = 0; k < 8; k++) {
            int s = __shfl_sync(FULLM, sv, k);
            float we = __shfl_sync(FULLM, w, k * 4 + hl);
            float4 xp = g_xproj[(size_t)s * 32 + lane];
            acc.x += we * xp.x; acc.y += we * xp.y;
            acc.z += we * xp.z; acc.w += we * xp.w;
        }
    }
    #pragma unroll
    for (int m = 4; m <= 16; m <<= 1) dsum += __shfl_xor_sync(FULLM, dsum, m);
    float denom = __shfl_sync(FULLM, dsum, hl);
    float inv = 1.0f / denom;
    float4 b4 = *(const float4*)(bias + lane * 4);
    float4 o;
    o.x = acc.x * inv + b4.x;
    o.y = acc.y * inv + b4.y;
    o.z = acc.z * inv + b4.z;
    o.w = acc.w * inv + b4.w;
    *(float4*)(out + (size_t)i * KHC + lane * 4) = o;
}

// ---------------- launch (single stream — fork experiment reverted) ----------------
extern "C" void kernel_launch(void* const* d_in, const int* in_sizes, int n_in,
                              void* d_out, int out_size) {
    const float* x         = (const float*)d_in[0];
    const int*   edge_idx  = (const int*)d_in[1];
    const float* edge_attr = (const float*)d_in[2];
    const float* W         = (const float*)d_in[3];
    const float* att_src   = (const float*)d_in[4];
    const float* att_dst   = (const float*)d_in[5];
    const float* W_edge    = (const float*)d_in[6];
    const float* att_edge  = (const float*)d_in[7];
    const float* bias      = (const float*)d_in[8];
    float* out = (float*)d_out;

    int n = in_sizes[0] / KIN;       // 100000
    int E = in_sizes[1] / 2;         // 1600000
    int nb = (E + 31) / 32;

    k_reset<<<(n + 255) / 256, 256>>>(n);
    k_w2<<<1, 256>>>(W_edge, att_edge);
    k_gemm<<<(n + 127) / 128, 256>>>(x, W, n);
    k_attn<<<(n + 7) / 8, 256>>>(att_src, att_dst, n);
    k_hist<<<(E + 255) / 256, 256>>>(edge_idx, E);
    k_scan<<<1, 1024>>>(n);
    k_scatter<<<nb, 256>>>(edge_idx, edge_attr, E);
    k_psum<<<64, 256>>>(nb);
    k_agg<<<(n + 7) / 8, 256>>>(bias, out, n, 1.0f / (float)E);
}

// round 8
// speedup vs baseline: 1.2291x; 1.1978x over previous
#include <cuda_runtime.h>
#include <cuda_bf16.h>
#include <cstdint>

#define KN      100000
#define KE      1600000
#define KIN     256
#define KED     64
#define KH      4
#define KC      32
#define KHC     128
#define KNB     ((KE + 7) / 8)

#define FULLM 0xFFFFFFFFu

// ---------------- scratch (static device globals; no allocation) ----------------
__device__ float4 g_xproj[KN * 32];        // [N][128]  (51.2 MB)
__device__ float4 g_asrc[KN];
__device__ float4 g_adst[KN];
__device__ float  g_W2[KED * KH];          // [64][4]
__device__ float  g_loopsum[KH];
__device__ int    g_deg[KN];
__device__ int    g_off[KN + 1];
__device__ int    g_cursor[KN];
__device__ int    g_ssrc[KE];
__device__ float4 g_salpha[KE];            // (25.6 MB)
__device__ float4 g_part[KNB];

// ---------------- reset ----------------
__global__ void k_reset(int n) {
    int i = blockIdx.x * blockDim.x + threadIdx.x;
    if (i < n) g_deg[i] = 0;
    if (i < KH) g_loopsum[i] = 0.f;
}

// ---------------- W2[d][h] = sum_c W_edge[d, h*32+c] * att_edge[h, c] ----------------
__global__ void k_w2(const float* __restrict__ W_edge, const float* __restrict__ att_edge) {
    int t = threadIdx.x;                 // 256 threads
    int d = t >> 2, h = t & 3;
    float s = 0.f;
    #pragma unroll 8
    for (int c = 0; c < KC; c++)
        s += W_edge[d * KHC + h * KC + c] * att_edge[h * KC + c];
    g_W2[d * KH + h] = s;
}

// ---------------- GEMM: x_proj = x[N,256] @ W[256,128] ----------------
// 256 threads, tile 128x128, k-chunk 16, 8x8 microtile.
// Software-pipelined: register-staged LDG for chunk c+1 issued before compute of c,
// double-buffered smem, ONE __syncthreads per chunk.
__global__ __launch_bounds__(256) void k_gemm(const float* __restrict__ x,
                                              const float* __restrict__ W, int n) {
    __shared__ float Xs[2][16][128];
    __shared__ float Ws[2][16][128];
    int tid = threadIdx.x;
    int bm = blockIdx.x * 128;
    int tx = tid & 15;           // 0..15
    int ty = tid >> 4;           // 0..15

    float acc[8][8];
    #pragma unroll
    for (int i = 0; i < 8; i++)
        #pragma unroll
        for (int j = 0; j < 8; j++) acc[i][j] = 0.f;

    int xr = tid >> 2;           // 0..63  (row within half-tile)
    int xk = (tid & 3) << 2;     // 0,4,8,12
    int wk = tid >> 5;           // 0..7
    int wn = (tid & 31) << 2;    // 0..124

    int gm0 = bm + xr;
    int gm1 = bm + xr + 64;
    const float* xrow0 = x + (size_t)(gm0 < n ? gm0 : 0) * KIN + xk;
    const float* xrow1 = x + (size_t)(gm1 < n ? gm1 : 0) * KIN + xk;
    bool v0 = gm0 < n, v1 = gm1 < n;
    const float* wrow0 = W + (size_t)wk * KHC + wn;
    const float* wrow1 = W + (size_t)(wk + 8) * KHC + wn;
    const float4 z4 = make_float4(0.f, 0.f, 0.f, 0.f);

    // prologue: chunk 0 into registers
    float4 xv0 = v0 ? *(const float4*)(xrow0) : z4;
    float4 xv1 = v1 ? *(const float4*)(xrow1) : z4;
    float4 wv0 = *(const float4*)(wrow0);
    float4 wv1 = *(const float4*)(wrow1);

    #pragma unroll 1
    for (int c = 0; c < 16; c++) {
        int s = c & 1;
        // store staged chunk c (X transposed)
        Xs[s][xk + 0][xr] = xv0.x;
        Xs[s][xk + 1][xr] = xv0.y;
        Xs[s][xk + 2][xr] = xv0.z;
        Xs[s][xk + 3][xr] = xv0.w;
        Xs[s][xk + 0][xr + 64] = xv1.x;
        Xs[s][xk + 1][xr + 64] = xv1.y;
        Xs[s][xk + 2][xr + 64] = xv1.z;
        Xs[s][xk + 3][xr + 64] = xv1.w;
        *(float4*)&Ws[s][wk][wn] = wv0;
        *(float4*)&Ws[s][wk + 8][wn] = wv1;
        __syncthreads();
        // issue next chunk's loads (in flight behind compute)
        if (c < 15) {
            int kb = (c + 1) * 16;
            xv0 = v0 ? *(const float4*)(xrow0 + kb) : z4;
            xv1 = v1 ? *(const float4*)(xrow1 + kb) : z4;
            wv0 = *(const float4*)(wrow0 + (size_t)kb * KHC);
            wv1 = *(const float4*)(wrow1 + (size_t)kb * KHC);
        }
        // compute chunk c
        #pragma unroll
        for (int k = 0; k < 16; k++) {
            float4 a0 = *(const float4*)&Xs[s][k][ty * 8];
            float4 a1 = *(const float4*)&Xs[s][k][ty * 8 + 4];
            float4 b0 = *(const float4*)&Ws[s][k][tx * 4];
            float4 b1 = *(const float4*)&Ws[s][k][tx * 4 + 64];
            float av[8] = {a0.x, a0.y, a0.z, a0.w, a1.x, a1.y, a1.z, a1.w};
            float bv[8] = {b0.x, b0.y, b0.z, b0.w, b1.x, b1.y, b1.z, b1.w};
            #pragma unroll
            for (int i = 0; i < 8; i++)
                #pragma unroll
                for (int j = 0; j < 8; j++)
                    acc[i][j] += av[i] * bv[j];
        }
        // no second barrier: next iteration writes the OTHER buffer, and its
        // barrier orders those stores against this chunk's reads.
    }
    #pragma unroll
    for (int i = 0; i < 8; i++) {
        int gm = bm + ty * 8 + i;
        if (gm < n) {
            g_xproj[(size_t)gm * 32 + tx] =
                make_float4(acc[i][0], acc[i][1], acc[i][2], acc[i][3]);
            g_xproj[(size_t)gm * 32 + 16 + tx] =
                make_float4(acc[i][4], acc[i][5], acc[i][6], acc[i][7]);
        }
    }
}

// ---------------- a_src / a_dst: warp per node ----------------
__global__ void k_attn(const float* __restrict__ att_src,
                       const float* __restrict__ att_dst, int n) {
    int warp = (blockIdx.x * blockDim.x + threadIdx.x) >> 5;
    int lane = threadIdx.x & 31;
    if (warp >= n) return;
    float4 xp = g_xproj[(size_t)warp * 32 + lane];
    float4 as = *(const float4*)(att_src + lane * 4);
    float4 ad = *(const float4*)(att_dst + lane * 4);
    float ds = xp.x * as.x + xp.y * as.y + xp.z * as.z + xp.w * as.w;
    float dd = xp.x * ad.x + xp.y * ad.y + xp.z * ad.z + xp.w * ad.w;
    #pragma unroll
    for (int m = 1; m <= 4; m <<= 1) {
        ds += __shfl_xor_sync(FULLM, ds, m);
        dd += __shfl_xor_sync(FULLM, dd, m);
    }
    if ((lane & 7) == 0) {
        int h = lane >> 3;
        ((float*)&g_asrc[warp])[h] = ds;
        ((float*)&g_adst[warp])[h] = dd;
    }
}

// ---------------- histogram of dst ----------------
__global__ void k_hist(const int* __restrict__ edge_index, int E) {
    int e = blockIdx.x * blockDim.x + threadIdx.x;
    if (e < E) atomicAdd(&g_deg[edge_index[E + e]], 1);
}

// ---------------- single-block scan ----------------
__global__ void k_scan(int n) {
    __shared__ int s[1024];
    int t = threadIdx.x;
    int chunk = (n + 1023) / 1024;
    int start = t * chunk;
    int sum = 0;
    for (int j = 0; j < chunk; j++) {
        int i = start + j;
        if (i < n) sum += g_deg[i];
    }
    s[t] = sum;
    __syncthreads();
    for (int o = 1; o < 1024; o <<= 1) {
        int v = (t >= o) ? s[t - o] : 0;
        __syncthreads();
        s[t] += v;
        __syncthreads();
    }
    int run = s[t] - sum;
    for (int j = 0; j < chunk; j++) {
        int i = start + j;
        if (i < n) {
            g_off[i] = run;
            g_cursor[i] = run;
            run += g_deg[i];
        }
    }
    if (t == 1023) g_off[n] = s[1023];
}

// ---------------- scatter: warp per edge (r2-proven) ----------------
__global__ __launch_bounds__(256) void k_scatter(const int* __restrict__ edge_index,
                                                 const float* __restrict__ edge_attr, int E) {
    __shared__ float Ws2[KED * KH];
    __shared__ float bp[KH];
    int tid = threadIdx.x;
    Ws2[tid] = g_W2[tid];
    if (tid < KH) bp[tid] = 0.f;
    __syncthreads();

    int e = (blockIdx.x * blockDim.x + tid) >> 5;
    int lane = tid & 31;
    if (e < E) {
        float ea0 = edge_attr[(size_t)e * KED + lane];
        float ea1 = edge_attr[(size_t)e * KED + 32 + lane];
        float p0 = ea0 * Ws2[lane * 4 + 0] + ea1 * Ws2[(lane + 32) * 4 + 0];
        float p1 = ea0 * Ws2[lane * 4 + 1] + ea1 * Ws2[(lane + 32) * 4 + 1];
        float p2 = ea0 * Ws2[lane * 4 + 2] + ea1 * Ws2[(lane + 32) * 4 + 2];
        float p3 = ea0 * Ws2[lane * 4 + 3] + ea1 * Ws2[(lane + 32) * 4 + 3];
        #pragma unroll
        for (int m = 16; m >= 1; m >>= 1) {
            p0 += __shfl_xor_sync(FULLM, p0, m);
            p1 += __shfl_xor_sync(FULLM, p1, m);
            p2 += __shfl_xor_sync(FULLM, p2, m);
            p3 += __shfl_xor_sync(FULLM, p3, m);
        }
        if (lane == 0) {
            atomicAdd(&bp[0], p0);
            atomicAdd(&bp[1], p1);
            atomicAdd(&bp[2], p2);
            atomicAdd(&bp[3], p3);
            int src = edge_index[e];
            int dst = edge_index[E + e];
            float4 as = g_asrc[src];
            int pos = atomicAdd(&g_cursor[dst], 1);
            g_ssrc[pos] = src;
            g_salpha[pos] = make_float4(as.x + p0, as.y + p1, as.z + p2, as.w + p3);
        }
    }
    __syncthreads();
    if (tid < KH) ((float*)&g_part[blockIdx.x])[tid] = bp[tid];
}

// ---------------- reduce per-block p-sums ----------------
__global__ void k_psum(int nb) {
    int tid = blockIdx.x * blockDim.x + threadIdx.x;
    int stride = gridDim.x * blockDim.x;
    float4 s = make_float4(0.f, 0.f, 0.f, 0.f);
    for (int j = tid; j < nb; j += stride) {
        float4 v = g_part[j];
        s.x += v.x; s.y += v.y; s.z += v.z; s.w += v.w;
    }
    #pragma unroll
    for (int m = 16; m >= 1; m >>= 1) {
        s.x += __shfl_xor_sync(FULLM, s.x, m);
        s.y += __shfl_xor_sync(FULLM, s.y, m);
        s.z += __shfl_xor_sync(FULLM, s.z, m);
        s.w += __shfl_xor_sync(FULLM, s.w, m);
    }
    __shared__ float4 ws[8];
    int warp = threadIdx.x >> 5;
    int lane = threadIdx.x & 31;
    if (lane == 0) ws[warp] = s;
    __syncthreads();
    if (warp == 0) {
        float4 v = (lane < 8) ? ws[lane] : make_float4(0.f, 0.f, 0.f, 0.f);
        #pragma unroll
        for (int m = 4; m >= 1; m >>= 1) {
            v.x += __shfl_xor_sync(FULLM, v.x, m);
            v.y += __shfl_xor_sync(FULLM, v.y, m);
            v.z += __shfl_xor_sync(FULLM, v.z, m);
            v.w += __shfl_xor_sync(FULLM, v.w, m);
        }
        if (lane == 0) {
            atomicAdd(&g_loopsum[0], v.x);
            atomicAdd(&g_loopsum[1], v.y);
            atomicAdd(&g_loopsum[2], v.z);
            atomicAdd(&g_loopsum[3], v.w);
        }
    }
}

// ---------------- aggregation: warp per node, fused softmax + weighted sum ----------------
__global__ __launch_bounds__(256) void k_agg(const float* __restrict__ bias,
                                             float* __restrict__ out, int n, float invE) {
    int i = (blockIdx.x * blockDim.x + threadIdx.x) >> 5;
    int lane = threadIdx.x & 31;
    if (i >= n) return;

    int hl = lane >> 3;
    int sub = lane & 3;

    float adst_s = ((const float*)&g_adst[i])[sub];
    float asrc_s = ((const float*)&g_asrc[i])[sub];
    float lae_s  = g_loopsum[sub] * invE;
    float4 xpi = g_xproj[(size_t)i * 32 + lane];

    float4 acc = make_float4(0.f, 0.f, 0.f, 0.f);
    float dsum = 0.f;

    float vs = asrc_s + adst_s + lae_s;
    vs = vs > 0.f ? vs : 0.2f * vs;
    float ws = __expf(vs);
    if (lane < 4) dsum += ws;
    {
        float w = __shfl_sync(FULLM, ws, hl);
        acc.x += w * xpi.x; acc.y += w * xpi.y; acc.z += w * xpi.z; acc.w += w * xpi.w;
    }

    int beg = g_off[i], end = g_off[i + 1];
    const float* salpha_f = (const float*)g_salpha;
    for (int base = beg; base < end; base += 8) {
        int myedge = base + (lane >> 2);
        float w = 0.f;
        if (myedge < end) {
            float a = salpha_f[(size_t)base * 4 + lane] + adst_s;
            a = a > 0.f ? a : 0.2f * a;
            w = __expf(a);
        }
        dsum += w;
        int sv = i;
        if (lane < 8 && base + lane < end) sv = g_ssrc[base + lane];
        #pragma unroll
        for (int k = 0; k < 8; k++) {
            int s = __shfl_sync(FULLM, sv, k);
            float we = __shfl_sync(FULLM, w, k * 4 + hl);
            float4 xp = g_xproj[(size_t)s * 32 + lane];
            acc.x += we * xp.x; acc.y += we * xp.y;
            acc.z += we * xp.z; acc.w += we * xp.w;
        }
    }
    #pragma unroll
    for (int m = 4; m <= 16; m <<= 1) dsum += __shfl_xor_sync(FULLM, dsum, m);
    float denom = __shfl_sync(FULLM, dsum, hl);
    float inv = 1.0f / denom;
    float4 b4 = *(const float4*)(bias + lane * 4);
    float4 o;
    o.x = acc.x * inv + b4.x;
    o.y = acc.y * inv + b4.y;
    o.z = acc.z * inv + b4.z;
    o.w = acc.w * inv + b4.w;
    *(float4*)(out + (size_t)i * KHC + lane * 4) = o;
}

// ---------------- launch (k_gemm placed 4th for ncu capture) ----------------
extern "C" void kernel_launch(void* const* d_in, const int* in_sizes, int n_in,
                              void* d_out, int out_size) {
    const float* x         = (const float*)d_in[0];
    const int*   edge_idx  = (const int*)d_in[1];
    const float* edge_attr = (const float*)d_in[2];
    const float* W         = (const float*)d_in[3];
    const float* att_src   = (const float*)d_in[4];
    const float* att_dst   = (const float*)d_in[5];
    const float* W_edge    = (const float*)d_in[6];
    const float* att_edge  = (const float*)d_in[7];
    const float* bias      = (const float*)d_in[8];
    float* out = (float*)d_out;

    int n = in_sizes[0] / KIN;       // 100000
    int E = in_sizes[1] / 2;         // 1600000
    int nb = (E + 7) / 8;

    k_reset<<<(n + 255) / 256, 256>>>(n);
    k_w2<<<1, 256>>>(W_edge, att_edge);
    k_hist<<<(E + 255) / 256, 256>>>(edge_idx, E);
    k_gemm<<<(n + 127) / 128, 256>>>(x, W, n);      // launch #4 -> profiled
    k_attn<<<(n + 7) / 8, 256>>>(att_src, att_dst, n);
    k_scan<<<1, 1024>>>(n);
    k_scatter<<<nb, 256>>>(edge_idx, edge_attr, E);
    k_psum<<<64, 256>>>(nb);
    k_agg<<<(n + 7) / 8, 256>>>(bias, out, n, 1.0f / (float)E);
}

// round 9
// speedup vs baseline: 2.0824x; 1.6943x over previous
#include <cuda_runtime.h>
#include <cuda_bf16.h>
#include <cstdint>

#define KN      100000
#define KE      1600000
#define KIN     256
#define KED     64
#define KH      4
#define KC      32
#define KHC     128

#define FULLM 0xFFFFFFFFu

// ---------------- scratch (static device globals; no allocation) ----------------
__device__ float4 g_xproj[KN * 32];        // [N][128]  (51.2 MB)
__device__ float4 g_asrc[KN];
__device__ float4 g_adst[KN];
__device__ float  g_W2[KED * KH];          // [64][4]
__device__ float  g_loopsum[KH];
__device__ int    g_deg[KN];
__device__ int    g_off[KN + 1];
__device__ int    g_cursor[KN];
__device__ int    g_bsum[512];
__device__ int    g_boff[512];
__device__ int    g_ssrc[KE];
__device__ float4 g_salpha[KE];            // (25.6 MB)
__device__ float4 g_ealpha[KE];            // (25.6 MB) per-edge a_edge

// ---------------- reset ----------------
__global__ void k_reset(int n) {
    int i = blockIdx.x * blockDim.x + threadIdx.x;
    if (i < n) g_deg[i] = 0;
    if (i < KH) g_loopsum[i] = 0.f;
}

// ---------------- W2[d][h] = sum_c W_edge[d, h*32+c] * att_edge[h, c] ----------------
__global__ void k_w2(const float* __restrict__ W_edge, const float* __restrict__ att_edge) {
    int t = threadIdx.x;                 // 256 threads
    int d = t >> 2, h = t & 3;
    float s = 0.f;
    #pragma unroll 8
    for (int c = 0; c < KC; c++)
        s += W_edge[d * KHC + h * KC + c] * att_edge[h * KC + c];
    g_W2[d * KH + h] = s;
}

// ---------------- histogram of dst ----------------
__global__ void k_hist(const int* __restrict__ edge_index, int E) {
    int e = blockIdx.x * blockDim.x + threadIdx.x;
    if (e < E) atomicAdd(&g_deg[edge_index[E + e]], 1);
}

// ---------------- escore: per-edge a_edge matvec + loopsum (streaming, grid-stride) ----------------
__global__ __launch_bounds__(256) void k_escore(const float* __restrict__ edge_attr, int E) {
    __shared__ float Ws2[KED * KH];
    __shared__ float bp[KH];
    int tid = threadIdx.x;
    Ws2[tid] = g_W2[tid];
    if (tid < KH) bp[tid] = 0.f;
    __syncthreads();

    int lane = tid & 31, wid = tid >> 5;
    int warp0 = blockIdx.x * 8 + wid;
    int nw = gridDim.x * 8;
    float w00 = Ws2[lane * 4 + 0], w01 = Ws2[lane * 4 + 1];
    float w02 = Ws2[lane * 4 + 2], w03 = Ws2[lane * 4 + 3];
    float w10 = Ws2[(lane + 32) * 4 + 0], w11 = Ws2[(lane + 32) * 4 + 1];
    float w12 = Ws2[(lane + 32) * 4 + 2], w13 = Ws2[(lane + 32) * 4 + 3];

    float s0 = 0.f, s1 = 0.f, s2 = 0.f, s3 = 0.f;
    for (int e = warp0; e < E; e += nw) {
        float ea0 = edge_attr[(size_t)e * KED + lane];
        float ea1 = edge_attr[(size_t)e * KED + 32 + lane];
        float p0 = ea0 * w00 + ea1 * w10;
        float p1 = ea0 * w01 + ea1 * w11;
        float p2 = ea0 * w02 + ea1 * w12;
        float p3 = ea0 * w03 + ea1 * w13;
        #pragma unroll
        for (int m = 16; m >= 1; m >>= 1) {
            p0 += __shfl_xor_sync(FULLM, p0, m);
            p1 += __shfl_xor_sync(FULLM, p1, m);
            p2 += __shfl_xor_sync(FULLM, p2, m);
            p3 += __shfl_xor_sync(FULLM, p3, m);
        }
        if (lane == 0) {
            g_ealpha[e] = make_float4(p0, p1, p2, p3);
            s0 += p0; s1 += p1; s2 += p2; s3 += p3;
        }
    }
    if (lane == 0) {
        atomicAdd(&bp[0], s0);
        atomicAdd(&bp[1], s1);
        atomicAdd(&bp[2], s2);
        atomicAdd(&bp[3], s3);
    }
    __syncthreads();
    if (tid < KH) atomicAdd(&g_loopsum[tid], bp[tid]);
}

// ---------------- GEMM: x_proj = x[N,256] @ W[256,128]  (r8 pipelined, 167us) ----------------
__global__ __launch_bounds__(256) void k_gemm(const float* __restrict__ x,
                                              const float* __restrict__ W, int n) {
    __shared__ float Xs[2][16][128];
    __shared__ float Ws[2][16][128];
    int tid = threadIdx.x;
    int bm = blockIdx.x * 128;
    int tx = tid & 15;
    int ty = tid >> 4;

    float acc[8][8];
    #pragma unroll
    for (int i = 0; i < 8; i++)
        #pragma unroll
        for (int j = 0; j < 8; j++) acc[i][j] = 0.f;

    int xr = tid >> 2;
    int xk = (tid & 3) << 2;
    int wk = tid >> 5;
    int wn = (tid & 31) << 2;

    int gm0 = bm + xr;
    int gm1 = bm + xr + 64;
    const float* xrow0 = x + (size_t)(gm0 < n ? gm0 : 0) * KIN + xk;
    const float* xrow1 = x + (size_t)(gm1 < n ? gm1 : 0) * KIN + xk;
    bool v0 = gm0 < n, v1 = gm1 < n;
    const float* wrow0 = W + (size_t)wk * KHC + wn;
    const float* wrow1 = W + (size_t)(wk + 8) * KHC + wn;
    const float4 z4 = make_float4(0.f, 0.f, 0.f, 0.f);

    float4 xv0 = v0 ? *(const float4*)(xrow0) : z4;
    float4 xv1 = v1 ? *(const float4*)(xrow1) : z4;
    float4 wv0 = *(const float4*)(wrow0);
    float4 wv1 = *(const float4*)(wrow1);

    #pragma unroll 1
    for (int c = 0; c < 16; c++) {
        int s = c & 1;
        Xs[s][xk + 0][xr] = xv0.x;
        Xs[s][xk + 1][xr] = xv0.y;
        Xs[s][xk + 2][xr] = xv0.z;
        Xs[s][xk + 3][xr] = xv0.w;
        Xs[s][xk + 0][xr + 64] = xv1.x;
        Xs[s][xk + 1][xr + 64] = xv1.y;
        Xs[s][xk + 2][xr + 64] = xv1.z;
        Xs[s][xk + 3][xr + 64] = xv1.w;
        *(float4*)&Ws[s][wk][wn] = wv0;
        *(float4*)&Ws[s][wk + 8][wn] = wv1;
        __syncthreads();
        if (c < 15) {
            int kb = (c + 1) * 16;
            xv0 = v0 ? *(const float4*)(xrow0 + kb) : z4;
            xv1 = v1 ? *(const float4*)(xrow1 + kb) : z4;
            wv0 = *(const float4*)(wrow0 + (size_t)kb * KHC);
            wv1 = *(const float4*)(wrow1 + (size_t)kb * KHC);
        }
        #pragma unroll
        for (int k = 0; k < 16; k++) {
            float4 a0 = *(const float4*)&Xs[s][k][ty * 8];
            float4 a1 = *(const float4*)&Xs[s][k][ty * 8 + 4];
            float4 b0 = *(const float4*)&Ws[s][k][tx * 4];
            float4 b1 = *(const float4*)&Ws[s][k][tx * 4 + 64];
            float av[8] = {a0.x, a0.y, a0.z, a0.w, a1.x, a1.y, a1.z, a1.w};
            float bv[8] = {b0.x, b0.y, b0.z, b0.w, b1.x, b1.y, b1.z, b1.w};
            #pragma unroll
            for (int i = 0; i < 8; i++)
                #pragma unroll
                for (int j = 0; j < 8; j++)
                    acc[i][j] += av[i] * bv[j];
        }
    }
    #pragma unroll
    for (int i = 0; i < 8; i++) {
        int gm = bm + ty * 8 + i;
        if (gm < n) {
            g_xproj[(size_t)gm * 32 + tx] =
                make_float4(acc[i][0], acc[i][1], acc[i][2], acc[i][3]);
            g_xproj[(size_t)gm * 32 + 16 + tx] =
                make_float4(acc[i][4], acc[i][5], acc[i][6], acc[i][7]);
        }
    }
}

// ---------------- a_src / a_dst: warp per node ----------------
__global__ void k_attn(const float* __restrict__ att_src,
                       const float* __restrict__ att_dst, int n) {
    int warp = (blockIdx.x * blockDim.x + threadIdx.x) >> 5;
    int lane = threadIdx.x & 31;
    if (warp >= n) return;
    float4 xp = g_xproj[(size_t)warp * 32 + lane];
    float4 as = *(const float4*)(att_src + lane * 4);
    float4 ad = *(const float4*)(att_dst + lane * 4);
    float ds = xp.x * as.x + xp.y * as.y + xp.z * as.z + xp.w * as.w;
    float dd = xp.x * ad.x + xp.y * ad.y + xp.z * ad.z + xp.w * ad.w;
    #pragma unroll
    for (int m = 1; m <= 4; m <<= 1) {
        ds += __shfl_xor_sync(FULLM, ds, m);
        dd += __shfl_xor_sync(FULLM, dd, m);
    }
    if ((lane & 7) == 0) {
        int h = lane >> 3;
        ((float*)&g_asrc[warp])[h] = ds;
        ((float*)&g_adst[warp])[h] = dd;
    }
}

// ---------------- 3-stage chip-wide exclusive scan of g_deg ----------------
__global__ void k_scan1(int n) {
    __shared__ int s[256];
    int t = threadIdx.x;
    int i = blockIdx.x * 256 + t;
    int v = (i < n) ? g_deg[i] : 0;
    s[t] = v;
    __syncthreads();
    #pragma unroll
    for (int o = 128; o > 0; o >>= 1) {
        if (t < o) s[t] += s[t + o];
        __syncthreads();
    }
    if (t == 0) g_bsum[blockIdx.x] = s[0];
}

__global__ void k_scan2(int nb, int n) {
    __shared__ int s[512];
    int t = threadIdx.x;
    int v = (t < nb) ? g_bsum[t] : 0;
    s[t] = v;
    __syncthreads();
    #pragma unroll
    for (int o = 1; o < 512; o <<= 1) {
        int u = (t >= o) ? s[t - o] : 0;
        __syncthreads();
        s[t] += u;
        __syncthreads();
    }
    if (t < nb) g_boff[t] = s[t] - v;     // exclusive block offset
    if (t == 511) g_off[n] = s[511];      // total
}

__global__ void k_scan3(int n) {
    __shared__ int s[256];
    int t = threadIdx.x;
    int i = blockIdx.x * 256 + t;
    int v = (i < n) ? g_deg[i] : 0;
    s[t] = v;
    __syncthreads();
    #pragma unroll
    for (int o = 1; o < 256; o <<= 1) {
        int u = (t >= o) ? s[t - o] : 0;
        __syncthreads();
        s[t] += u;
        __syncthreads();
    }
    if (i < n) {
        int off = g_boff[blockIdx.x] + s[t] - v;   // exclusive
        g_off[i] = off;
        g_cursor[i] = off;
    }
}

// ---------------- scatter: thread per edge (256 independent chains/block) ----------------
__global__ __launch_bounds__(256) void k_scat(const int* __restrict__ edge_index, int E) {
    int e = blockIdx.x * 256 + threadIdx.x;
    if (e >= E) return;
    int src = edge_index[e];
    int dst = edge_index[E + e];
    float4 p = g_ealpha[e];
    float4 as = g_asrc[src];
    int pos = atomicAdd(&g_cursor[dst], 1);
    g_ssrc[pos] = src;
    g_salpha[pos] = make_float4(as.x + p.x, as.y + p.y, as.z + p.z, as.w + p.w);
}

// ---------------- aggregation: warp per node, fused softmax + weighted sum ----------------
__global__ __launch_bounds__(256) void k_agg(const float* __restrict__ bias,
                                             float* __restrict__ out, int n, float invE) {
    int i = (blockIdx.x * blockDim.x + threadIdx.x) >> 5;
    int lane = threadIdx.x & 31;
    if (i >= n) return;

    int hl = lane >> 3;
    int sub = lane & 3;

    float adst_s = ((const float*)&g_adst[i])[sub];
    float asrc_s = ((const float*)&g_asrc[i])[sub];
    float lae_s  = g_loopsum[sub] * invE;
    float4 xpi = g_xproj[(size_t)i * 32 + lane];

    float4 acc = make_float4(0.f, 0.f, 0.f, 0.f);
    float dsum = 0.f;

    float vs = asrc_s + adst_s + lae_s;
    vs = vs > 0.f ? vs : 0.2f * vs;
    float ws = __expf(vs);
    if (lane < 4) dsum += ws;
    {
        float w = __shfl_sync(FULLM, ws, hl);
        acc.x += w * xpi.x; acc.y += w * xpi.y; acc.z += w * xpi.z; acc.w += w * xpi.w;
    }

    int beg = g_off[i], end = g_off[i + 1];
    const float* salpha_f = (const float*)g_salpha;
    for (int base = beg; base < end; base += 8) {
        int myedge = base + (lane >> 2);
        float w = 0.f;
        if (myedge < end) {
            float a = salpha_f[(size_t)base * 4 + lane] + adst_s;
            a = a > 0.f ? a : 0.2f * a;
            w = __expf(a);
        }
        dsum += w;
        int sv = i;
        if (lane < 8 && base + lane < end) sv = g_ssrc[base + lane];
        #pragma unroll
        for (int k = 0; k < 8; k++) {
            int s = __shfl_sync(FULLM, sv, k);
            float we = __shfl_sync(FULLM, w, k * 4 + hl);
            float4 xp = g_xproj[(size_t)s * 32 + lane];
            acc.x += we * xp.x; acc.y += we * xp.y;
            acc.z += we * xp.z; acc.w += we * xp.w;
        }
    }
    #pragma unroll
    for (int m = 4; m <= 16; m <<= 1) dsum += __shfl_xor_sync(FULLM, dsum, m);
    float denom = __shfl_sync(FULLM, dsum, hl);
    float inv = 1.0f / denom;
    float4 b4 = *(const float4*)(bias + lane * 4);
    float4 o;
    o.x = acc.x * inv + b4.x;
    o.y = acc.y * inv + b4.y;
    o.z = acc.z * inv + b4.z;
    o.w = acc.w * inv + b4.w;
    *(float4*)(out + (size_t)i * KHC + lane * 4) = o;
}

// ---------------- launch (k_escore at #4 for ncu capture) ----------------
extern "C" void kernel_launch(void* const* d_in, const int* in_sizes, int n_in,
                              void* d_out, int out_size) {
    const float* x         = (const float*)d_in[0];
    const int*   edge_idx  = (const int*)d_in[1];
    const float* edge_attr = (const float*)d_in[2];
    const float* W         = (const float*)d_in[3];
    const float* att_src   = (const float*)d_in[4];
    const float* att_dst   = (const float*)d_in[5];
    const float* W_edge    = (const float*)d_in[6];
    const float* att_edge  = (const float*)d_in[7];
    const float* bias      = (const float*)d_in[8];
    float* out = (float*)d_out;

    int n = in_sizes[0] / KIN;       // 100000
    int E = in_sizes[1] / 2;         // 1600000
    int nblk = (n + 255) / 256;      // 391

    k_reset<<<nblk, 256>>>(n);
    k_w2<<<1, 256>>>(W_edge, att_edge);
    k_hist<<<(E + 255) / 256, 256>>>(edge_idx, E);
    k_escore<<<2048, 256>>>(edge_attr, E);          // launch #4 -> profiled
    k_gemm<<<(n + 127) / 128, 256>>>(x, W, n);
    k_attn<<<(n + 7) / 8, 256>>>(att_src, att_dst, n);
    k_scan1<<<nblk, 256>>>(n);
    k_scan2<<<1, 512>>>(nblk, n);
    k_scan3<<<nblk, 256>>>(n);
    k_scat<<<(E + 255) / 256, 256>>>(edge_idx, E);
    k_agg<<<(n + 7) / 8, 256>>>(bias, out, n, 1.0f / (float)E);
}

// round 10
// speedup vs baseline: 2.1797x; 1.0467x over previous
#include <cuda_runtime.h>
#include <cuda_bf16.h>
#include <cstdint>

#define KN      100000
#define KE      1600000
#define KIN     256
#define KED     64
#define KH      4
#define KC      32
#define KHC     128

#define FULLM 0xFFFFFFFFu

// ---------------- scratch (static device globals; no allocation) ----------------
__device__ float4 g_xproj[KN * 32];        // [N][128]  (51.2 MB)
__device__ float4 g_asrc[KN];
__device__ float4 g_adst[KN];
__device__ float  g_W2[KED * KH];          // [64][4]
__device__ float  g_loopsum[KH];
__device__ int    g_deg[KN];
__device__ int    g_off[KN + 1];
__device__ int    g_cursor[KN];
__device__ int    g_bsum[512];
__device__ int    g_boff[512];
__device__ int    g_ssrc[KE];
__device__ float4 g_salpha[KE];            // (25.6 MB)

// ---------------- reset ----------------
__global__ void k_reset(int n) {
    int i = blockIdx.x * blockDim.x + threadIdx.x;
    if (i < n) g_deg[i] = 0;
    if (i < KH) g_loopsum[i] = 0.f;
}

// ---------------- W2[d][h] = sum_c W_edge[d, h*32+c] * att_edge[h, c] ----------------
__global__ void k_w2(const float* __restrict__ W_edge, const float* __restrict__ att_edge) {
    int t = threadIdx.x;                 // 256 threads
    int d = t >> 2, h = t & 3;
    float s = 0.f;
    #pragma unroll 8
    for (int c = 0; c < KC; c++)
        s += W_edge[d * KHC + h * KC + c] * att_edge[h * KC + c];
    g_W2[d * KH + h] = s;
}

// ---------------- histogram of dst ----------------
__global__ void k_hist(const int* __restrict__ edge_index, int E) {
    int e = blockIdx.x * blockDim.x + threadIdx.x;
    if (e < E) atomicAdd(&g_deg[edge_index[E + e]], 1);
}

// ---------------- GEMM: x_proj = x[N,256] @ W[256,128]  (r8 pipelined, FFMA-floor) ----------------
__global__ __launch_bounds__(256) void k_gemm(const float* __restrict__ x,
                                              const float* __restrict__ W, int n) {
    __shared__ float Xs[2][16][128];
    __shared__ float Ws[2][16][128];
    int tid = threadIdx.x;
    int bm = blockIdx.x * 128;
    int tx = tid & 15;
    int ty = tid >> 4;

    float acc[8][8];
    #pragma unroll
    for (int i = 0; i < 8; i++)
        #pragma unroll
        for (int j = 0; j < 8; j++) acc[i][j] = 0.f;

    int xr = tid >> 2;
    int xk = (tid & 3) << 2;
    int wk = tid >> 5;
    int wn = (tid & 31) << 2;

    int gm0 = bm + xr;
    int gm1 = bm + xr + 64;
    const float* xrow0 = x + (size_t)(gm0 < n ? gm0 : 0) * KIN + xk;
    const float* xrow1 = x + (size_t)(gm1 < n ? gm1 : 0) * KIN + xk;
    bool v0 = gm0 < n, v1 = gm1 < n;
    const float* wrow0 = W + (size_t)wk * KHC + wn;
    const float* wrow1 = W + (size_t)(wk + 8) * KHC + wn;
    const float4 z4 = make_float4(0.f, 0.f, 0.f, 0.f);

    float4 xv0 = v0 ? *(const float4*)(xrow0) : z4;
    float4 xv1 = v1 ? *(const float4*)(xrow1) : z4;
    float4 wv0 = *(const float4*)(wrow0);
    float4 wv1 = *(const float4*)(wrow1);

    #pragma unroll 1
    for (int c = 0; c < 16; c++) {
        int s = c & 1;
        Xs[s][xk + 0][xr] = xv0.x;
        Xs[s][xk + 1][xr] = xv0.y;
        Xs[s][xk + 2][xr] = xv0.z;
        Xs[s][xk + 3][xr] = xv0.w;
        Xs[s][xk + 0][xr + 64] = xv1.x;
        Xs[s][xk + 1][xr + 64] = xv1.y;
        Xs[s][xk + 2][xr + 64] = xv1.z;
        Xs[s][xk + 3][xr + 64] = xv1.w;
        *(float4*)&Ws[s][wk][wn] = wv0;
        *(float4*)&Ws[s][wk + 8][wn] = wv1;
        __syncthreads();
        if (c < 15) {
            int kb = (c + 1) * 16;
            xv0 = v0 ? *(const float4*)(xrow0 + kb) : z4;
            xv1 = v1 ? *(const float4*)(xrow1 + kb) : z4;
            wv0 = *(const float4*)(wrow0 + (size_t)kb * KHC);
            wv1 = *(const float4*)(wrow1 + (size_t)kb * KHC);
        }
        #pragma unroll
        for (int k = 0; k < 16; k++) {
            float4 a0 = *(const float4*)&Xs[s][k][ty * 8];
            float4 a1 = *(const float4*)&Xs[s][k][ty * 8 + 4];
            float4 b0 = *(const float4*)&Ws[s][k][tx * 4];
            float4 b1 = *(const float4*)&Ws[s][k][tx * 4 + 64];
            float av[8] = {a0.x, a0.y, a0.z, a0.w, a1.x, a1.y, a1.z, a1.w};
            float bv[8] = {b0.x, b0.y, b0.z, b0.w, b1.x, b1.y, b1.z, b1.w};
            #pragma unroll
            for (int i = 0; i < 8; i++)
                #pragma unroll
                for (int j = 0; j < 8; j++)
                    acc[i][j] += av[i] * bv[j];
        }
    }
    #pragma unroll
    for (int i = 0; i < 8; i++) {
        int gm = bm + ty * 8 + i;
        if (gm < n) {
            g_xproj[(size_t)gm * 32 + tx] =
                make_float4(acc[i][0], acc[i][1], acc[i][2], acc[i][3]);
            g_xproj[(size_t)gm * 32 + 16 + tx] =
                make_float4(acc[i][4], acc[i][5], acc[i][6], acc[i][7]);
        }
    }
}

// ---------------- a_src / a_dst: warp per node ----------------
__global__ void k_attn(const float* __restrict__ att_src,
                       const float* __restrict__ att_dst, int n) {
    int warp = (blockIdx.x * blockDim.x + threadIdx.x) >> 5;
    int lane = threadIdx.x & 31;
    if (warp >= n) return;
    float4 xp = g_xproj[(size_t)warp * 32 + lane];
    float4 as = *(const float4*)(att_src + lane * 4);
    float4 ad = *(const float4*)(att_dst + lane * 4);
    float ds = xp.x * as.x + xp.y * as.y + xp.z * as.z + xp.w * as.w;
    float dd = xp.x * ad.x + xp.y * ad.y + xp.z * ad.z + xp.w * ad.w;
    #pragma unroll
    for (int m = 1; m <= 4; m <<= 1) {
        ds += __shfl_xor_sync(FULLM, ds, m);
        dd += __shfl_xor_sync(FULLM, dd, m);
    }
    if ((lane & 7) == 0) {
        int h = lane >> 3;
        ((float*)&g_asrc[warp])[h] = ds;
        ((float*)&g_adst[warp])[h] = dd;
    }
}

// ---------------- 3-stage chip-wide exclusive scan of g_deg ----------------
__global__ void k_scan1(int n) {
    __shared__ int s[256];
    int t = threadIdx.x;
    int i = blockIdx.x * 256 + t;
    int v = (i < n) ? g_deg[i] : 0;
    s[t] = v;
    __syncthreads();
    #pragma unroll
    for (int o = 128; o > 0; o >>= 1) {
        if (t < o) s[t] += s[t + o];
        __syncthreads();
    }
    if (t == 0) g_bsum[blockIdx.x] = s[0];
}

__global__ void k_scan2(int nb, int n) {
    __shared__ int s[512];
    int t = threadIdx.x;
    int v = (t < nb) ? g_bsum[t] : 0;
    s[t] = v;
    __syncthreads();
    #pragma unroll
    for (int o = 1; o < 512; o <<= 1) {
        int u = (t >= o) ? s[t - o] : 0;
        __syncthreads();
        s[t] += u;
        __syncthreads();
    }
    if (t < nb) g_boff[t] = s[t] - v;     // exclusive block offset
    if (t == 511) g_off[n] = s[511];      // total
}

__global__ void k_scan3(int n) {
    __shared__ int s[256];
    int t = threadIdx.x;
    int i = blockIdx.x * 256 + t;
    int v = (i < n) ? g_deg[i] : 0;
    s[t] = v;
    __syncthreads();
    #pragma unroll
    for (int o = 1; o < 256; o <<= 1) {
        int u = (t >= o) ? s[t - o] : 0;
        __syncthreads();
        s[t] += u;
        __syncthreads();
    }
    if (i < n) {
        int off = g_boff[blockIdx.x] + s[t] - v;   // exclusive
        g_off[i] = off;
        g_cursor[i] = off;
    }
}

// ---------------- fused escore + scatter: 8 lanes/edge, grid-stride ----------------
__global__ __launch_bounds__(256) void k_scatf(const int* __restrict__ edge_index,
                                               const float* __restrict__ edge_attr, int E) {
    __shared__ float Ws2[KED * KH];
    __shared__ float bp[KH];
    int tid = threadIdx.x;
    Ws2[tid] = g_W2[tid];
    if (tid < KH) bp[tid] = 0.f;
    __syncthreads();

    int lane = tid & 31, wid = tid >> 5;
    int l8 = lane & 7, g8 = lane >> 3;
    int warp0 = blockIdx.x * 8 + wid;
    int NW = gridDim.x * 8;

    // per-lane weights for its 8 dims x 4 heads (registers)
    float wr[8][4];
    #pragma unroll
    for (int j = 0; j < 8; j++)
        #pragma unroll
        for (int h = 0; h < 4; h++)
            wr[j][h] = Ws2[(l8 * 8 + j) * 4 + h];

    float s0 = 0.f, s1 = 0.f, s2 = 0.f, s3 = 0.f;
    int gmax = (E + 3) >> 2;
    for (int g = warp0; g < gmax; g += NW) {
        int e = g * 4 + g8;
        bool valid = e < E;
        float p0 = 0.f, p1 = 0.f, p2 = 0.f, p3 = 0.f;
        if (valid) {
            const float* ea = edge_attr + (size_t)e * KED + l8 * 8;
            float4 v0 = *(const float4*)ea;
            float4 v1 = *(const float4*)(ea + 4);
            float av[8] = {v0.x, v0.y, v0.z, v0.w, v1.x, v1.y, v1.z, v1.w};
            #pragma unroll
            for (int j = 0; j < 8; j++) {
                p0 += av[j] * wr[j][0];
                p1 += av[j] * wr[j][1];
                p2 += av[j] * wr[j][2];
                p3 += av[j] * wr[j][3];
            }
        }
        #pragma unroll
        for (int m = 1; m <= 4; m <<= 1) {
            p0 += __shfl_xor_sync(FULLM, p0, m);
            p1 += __shfl_xor_sync(FULLM, p1, m);
            p2 += __shfl_xor_sync(FULLM, p2, m);
            p3 += __shfl_xor_sync(FULLM, p3, m);
        }
        if (l8 == 0 && valid) {
            int src = edge_index[e];
            int dst = edge_index[E + e];
            float4 as = g_asrc[src];
            int pos = atomicAdd(&g_cursor[dst], 1);
            g_ssrc[pos] = src;
            g_salpha[pos] = make_float4(as.x + p0, as.y + p1, as.z + p2, as.w + p3);
            s0 += p0; s1 += p1; s2 += p2; s3 += p3;
        }
    }
    if (l8 == 0) {
        atomicAdd(&bp[0], s0);
        atomicAdd(&bp[1], s1);
        atomicAdd(&bp[2], s2);
        atomicAdd(&bp[3], s3);
    }
    __syncthreads();
    if (tid < KH) atomicAdd(&g_loopsum[tid], bp[tid]);
}

// ---------------- aggregation: warp per node, fused softmax + weighted sum ----------------
__global__ __launch_bounds__(256) void k_agg(const float* __restrict__ bias,
                                             float* __restrict__ out, int n, float invE) {
    int i = (blockIdx.x * blockDim.x + threadIdx.x) >> 5;
    int lane = threadIdx.x & 31;
    if (i >= n) return;

    int hl = lane >> 3;
    int sub = lane & 3;

    float adst_s = ((const float*)&g_adst[i])[sub];
    float asrc_s = ((const float*)&g_asrc[i])[sub];
    float lae_s  = g_loopsum[sub] * invE;
    float4 xpi = g_xproj[(size_t)i * 32 + lane];

    float4 acc = make_float4(0.f, 0.f, 0.f, 0.f);
    float dsum = 0.f;

    float vs = asrc_s + adst_s + lae_s;
    vs = vs > 0.f ? vs : 0.2f * vs;
    float ws = __expf(vs);
    if (lane < 4) dsum += ws;
    {
        float w = __shfl_sync(FULLM, ws, hl);
        acc.x += w * xpi.x; acc.y += w * xpi.y; acc.z += w * xpi.z; acc.w += w * xpi.w;
    }

    int beg = g_off[i], end = g_off[i + 1];
    const float* salpha_f = (const float*)g_salpha;
    for (int base = beg; base < end; base += 8) {
        int myedge = base + (lane >> 2);
        float w = 0.f;
        if (myedge < end) {
            float a = salpha_f[(size_t)base * 4 + lane] + adst_s;
            a = a > 0.f ? a : 0.2f * a;
            w = __expf(a);
        }
        dsum += w;
        int sv = i;
        if (lane < 8 && base + lane < end) sv = g_ssrc[base + lane];
        #pragma unroll
        for (int k = 0; k < 8; k++) {
            int s = __shfl_sync(FULLM, sv, k);
            float we = __shfl_sync(FULLM, w, k * 4 + hl);
            float4 xp = g_xproj[(size_t)s * 32 + lane];
            acc.x += we * xp.x; acc.y += we * xp.y;
            acc.z += we * xp.z; acc.w += we * xp.w;
        }
    }
    #pragma unroll
    for (int m = 4; m <= 16; m <<= 1) dsum += __shfl_xor_sync(FULLM, dsum, m);
    float denom = __shfl_sync(FULLM, dsum, hl);
    float inv = 1.0f / denom;
    float4 b4 = *(const float4*)(bias + lane * 4);
    float4 o;
    o.x = acc.x * inv + b4.x;
    o.y = acc.y * inv + b4.y;
    o.z = acc.z * inv + b4.z;
    o.w = acc.w * inv + b4.w;
    *(float4*)(out + (size_t)i * KHC + lane * 4) = o;
}

// ---------------- launch (k_hist at #4 for ncu capture) ----------------
extern "C" void kernel_launch(void* const* d_in, const int* in_sizes, int n_in,
                              void* d_out, int out_size) {
    const float* x         = (const float*)d_in[0];
    const int*   edge_idx  = (const int*)d_in[1];
    const float* edge_attr = (const float*)d_in[2];
    const float* W         = (const float*)d_in[3];
    const float* att_src   = (const float*)d_in[4];
    const float* att_dst   = (const float*)d_in[5];
    const float* W_edge    = (const float*)d_in[6];
    const float* att_edge  = (const float*)d_in[7];
    const float* bias      = (const float*)d_in[8];
    float* out = (float*)d_out;

    int n = in_sizes[0] / KIN;       // 100000
    int E = in_sizes[1] / 2;         // 1600000
    int nblk = (n + 255) / 256;      // 391

    k_reset<<<nblk, 256>>>(n);
    k_w2<<<1, 256>>>(W_edge, att_edge);
    k_gemm<<<(n + 127) / 128, 256>>>(x, W, n);
    k_hist<<<(E + 255) / 256, 256>>>(edge_idx, E);   // launch #4 -> profiled
    k_attn<<<(n + 7) / 8, 256>>>(att_src, att_dst, n);
    k_scan1<<<nblk, 256>>>(n);
    k_scan2<<<1, 512>>>(nblk, n);
    k_scan3<<<nblk, 256>>>(n);
    k_scatf<<<2048, 256>>>(edge_idx, edge_attr, E);
    k_agg<<<(n + 7) / 8, 256>>>(bias, out, n, 1.0f / (float)E);
}

// round 11
// speedup vs baseline: 2.2499x; 1.0322x over previous
#include <cuda_runtime.h>
#include <cuda_bf16.h>
#include <cstdint>

#define KN      100000
#define KE      1600000
#define KIN     256
#define KED     64
#define KH      4
#define KC      32
#define KHC     128

#define FULLM 0xFFFFFFFFu

// ---------------- scratch (static device globals; no allocation) ----------------
__device__ float4 g_xproj[KN * 32];        // [N][128]  (51.2 MB)
__device__ float4 g_asrc[KN];
__device__ float4 g_adst[KN];
__device__ float  g_W2[KED * KH];          // [64][4]
__device__ float  g_loopsum[KH];
__device__ int    g_deg[KN];
__device__ int    g_off[KN + 1];
__device__ int    g_cursor[KN];
__device__ int    g_bsum[512];
__device__ int    g_boff[512];
__device__ int    g_ssrc[KE];
__device__ float4 g_salpha[KE];            // (25.6 MB)

// ---------------- reset ----------------
__global__ void k_reset(int n) {
    int i = blockIdx.x * blockDim.x + threadIdx.x;
    if (i < n) g_deg[i] = 0;
    if (i < KH) g_loopsum[i] = 0.f;
}

// ---------------- W2[d][h] = sum_c W_edge[d, h*32+c] * att_edge[h, c] ----------------
__global__ void k_w2(const float* __restrict__ W_edge, const float* __restrict__ att_edge) {
    int t = threadIdx.x;                 // 256 threads
    int d = t >> 2, h = t & 3;
    float s = 0.f;
    #pragma unroll 8
    for (int c = 0; c < KC; c++)
        s += W_edge[d * KHC + h * KC + c] * att_edge[h * KC + c];
    g_W2[d * KH + h] = s;
}

// ---------------- histogram of dst ----------------
__global__ void k_hist(const int* __restrict__ edge_index, int E) {
    int e = blockIdx.x * blockDim.x + threadIdx.x;
    if (e < E) atomicAdd(&g_deg[edge_index[E + e]], 1);
}

// ---------------- GEMM + fused a_src/a_dst epilogue ----------------
// 256 threads, tile 128x128, k-chunk 16, 8x8 microtile, reg-staged pipeline.
// launch_bounds(256,2): cap 128 regs -> 2 CTAs/SM.
__global__ __launch_bounds__(256, 2) void k_gemm(const float* __restrict__ x,
                                                 const float* __restrict__ W,
                                                 const float* __restrict__ att_src,
                                                 const float* __restrict__ att_dst, int n) {
    __shared__ float Xs[2][16][128];
    __shared__ float Ws[2][16][128];
    __shared__ float sred[128][8];     // [row][h0..3 = a_src, h4..7 = a_dst]
    int tid = threadIdx.x;
    int bm = blockIdx.x * 128;
    int tx = tid & 15;
    int ty = tid >> 4;

    // zero sred
    #pragma unroll
    for (int i = 0; i < 4; i++) ((float*)sred)[tid + i * 256] = 0.f;

    float acc[8][8];
    #pragma unroll
    for (int i = 0; i < 8; i++)
        #pragma unroll
        for (int j = 0; j < 8; j++) acc[i][j] = 0.f;

    int xr = tid >> 2;
    int xk = (tid & 3) << 2;
    int wk = tid >> 5;
    int wn = (tid & 31) << 2;

    int gm0 = bm + xr;
    int gm1 = bm + xr + 64;
    const float* xrow0 = x + (size_t)(gm0 < n ? gm0 : 0) * KIN + xk;
    const float* xrow1 = x + (size_t)(gm1 < n ? gm1 : 0) * KIN + xk;
    bool v0 = gm0 < n, v1 = gm1 < n;
    const float* wrow0 = W + (size_t)wk * KHC + wn;
    const float* wrow1 = W + (size_t)(wk + 8) * KHC + wn;
    const float4 z4 = make_float4(0.f, 0.f, 0.f, 0.f);

    float4 xv0 = v0 ? *(const float4*)(xrow0) : z4;
    float4 xv1 = v1 ? *(const float4*)(xrow1) : z4;
    float4 wv0 = *(const float4*)(wrow0);
    float4 wv1 = *(const float4*)(wrow1);

    #pragma unroll 1
    for (int c = 0; c < 16; c++) {
        int s = c & 1;
        Xs[s][xk + 0][xr] = xv0.x;
        Xs[s][xk + 1][xr] = xv0.y;
        Xs[s][xk + 2][xr] = xv0.z;
        Xs[s][xk + 3][xr] = xv0.w;
        Xs[s][xk + 0][xr + 64] = xv1.x;
        Xs[s][xk + 1][xr + 64] = xv1.y;
        Xs[s][xk + 2][xr + 64] = xv1.z;
        Xs[s][xk + 3][xr + 64] = xv1.w;
        *(float4*)&Ws[s][wk][wn] = wv0;
        *(float4*)&Ws[s][wk + 8][wn] = wv1;
        __syncthreads();
        if (c < 15) {
            int kb = (c + 1) * 16;
            xv0 = v0 ? *(const float4*)(xrow0 + kb) : z4;
            xv1 = v1 ? *(const float4*)(xrow1 + kb) : z4;
            wv0 = *(const float4*)(wrow0 + (size_t)kb * KHC);
            wv1 = *(const float4*)(wrow1 + (size_t)kb * KHC);
        }
        #pragma unroll
        for (int k = 0; k < 16; k++) {
            float4 a0 = *(const float4*)&Xs[s][k][ty * 8];
            float4 a1 = *(const float4*)&Xs[s][k][ty * 8 + 4];
            float4 b0 = *(const float4*)&Ws[s][k][tx * 4];
            float4 b1 = *(const float4*)&Ws[s][k][tx * 4 + 64];
            float av[8] = {a0.x, a0.y, a0.z, a0.w, a1.x, a1.y, a1.z, a1.w};
            float bv[8] = {b0.x, b0.y, b0.z, b0.w, b1.x, b1.y, b1.z, b1.w};
            #pragma unroll
            for (int i = 0; i < 8; i++)
                #pragma unroll
                for (int j = 0; j < 8; j++)
                    acc[i][j] += av[i] * bv[j];
        }
    }

    // store xproj
    #pragma unroll
    for (int i = 0; i < 8; i++) {
        int gm = bm + ty * 8 + i;
        if (gm < n) {
            g_xproj[(size_t)gm * 32 + tx] =
                make_float4(acc[i][0], acc[i][1], acc[i][2], acc[i][3]);
            g_xproj[(size_t)gm * 32 + 16 + tx] =
                make_float4(acc[i][4], acc[i][5], acc[i][6], acc[i][7]);
        }
    }

    // fused a_src / a_dst reduction
    float asr0[4], asr1[4], adr0[4], adr1[4];
    #pragma unroll
    for (int j = 0; j < 4; j++) {
        asr0[j] = att_src[tx * 4 + j];
        asr1[j] = att_src[64 + tx * 4 + j];
        adr0[j] = att_dst[tx * 4 + j];
        adr1[j] = att_dst[64 + tx * 4 + j];
    }
    int h0 = tx >> 3;        // head of cols [tx*4, tx*4+3]
    int h1 = 2 + (tx >> 3);  // head of cols [64+tx*4, ...]
    __syncthreads();         // sred zero visible (done before mainloop syncs, safe)
    #pragma unroll
    for (int i = 0; i < 8; i++) {
        int row = ty * 8 + i;
        float ps0 = acc[i][0] * asr0[0] + acc[i][1] * asr0[1] + acc[i][2] * asr0[2] + acc[i][3] * asr0[3];
        float pd0 = acc[i][0] * adr0[0] + acc[i][1] * adr0[1] + acc[i][2] * adr0[2] + acc[i][3] * adr0[3];
        float ps1 = acc[i][4] * asr1[0] + acc[i][5] * asr1[1] + acc[i][6] * asr1[2] + acc[i][7] * asr1[3];
        float pd1 = acc[i][4] * adr1[0] + acc[i][5] * adr1[1] + acc[i][6] * adr1[2] + acc[i][7] * adr1[3];
        atomicAdd(&sred[row][h0], ps0);
        atomicAdd(&sred[row][4 + h0], pd0);
        atomicAdd(&sred[row][h1], ps1);
        atomicAdd(&sred[row][4 + h1], pd1);
    }
    __syncthreads();
    if (tid < 128) {
        int gm = bm + tid;
        if (gm < n) {
            g_asrc[gm] = make_float4(sred[tid][0], sred[tid][1], sred[tid][2], sred[tid][3]);
            g_adst[gm] = make_float4(sred[tid][4], sred[tid][5], sred[tid][6], sred[tid][7]);
        }
    }
}

// ---------------- 3-stage chip-wide exclusive scan of g_deg ----------------
__global__ void k_scan1(int n) {
    __shared__ int s[256];
    int t = threadIdx.x;
    int i = blockIdx.x * 256 + t;
    int v = (i < n) ? g_deg[i] : 0;
    s[t] = v;
    __syncthreads();
    #pragma unroll
    for (int o = 128; o > 0; o >>= 1) {
        if (t < o) s[t] += s[t + o];
        __syncthreads();
    }
    if (t == 0) g_bsum[blockIdx.x] = s[0];
}

__global__ void k_scan2(int nb, int n) {
    __shared__ int s[512];
    int t = threadIdx.x;
    int v = (t < nb) ? g_bsum[t] : 0;
    s[t] = v;
    __syncthreads();
    #pragma unroll
    for (int o = 1; o < 512; o <<= 1) {
        int u = (t >= o) ? s[t - o] : 0;
        __syncthreads();
        s[t] += u;
        __syncthreads();
    }
    if (t < nb) g_boff[t] = s[t] - v;
    if (t == 511) g_off[n] = s[511];
}

__global__ void k_scan3(int n) {
    __shared__ int s[256];
    int t = threadIdx.x;
    int i = blockIdx.x * 256 + t;
    int v = (i < n) ? g_deg[i] : 0;
    s[t] = v;
    __syncthreads();
    #pragma unroll
    for (int o = 1; o < 256; o <<= 1) {
        int u = (t >= o) ? s[t - o] : 0;
        __syncthreads();
        s[t] += u;
        __syncthreads();
    }
    if (i < n) {
        int off = g_boff[blockIdx.x] + s[t] - v;
        g_off[i] = off;
        g_cursor[i] = off;
    }
}

// ---------------- fused escore + scatter: 8 lanes/edge, reg-prefetched grid-stride ----------------
__global__ __launch_bounds__(256) void k_scatf(const int* __restrict__ edge_index,
                                               const float* __restrict__ edge_attr, int E) {
    __shared__ float Ws2[KED * KH];
    __shared__ float bp[KH];
    int tid = threadIdx.x;
    Ws2[tid] = g_W2[tid];
    if (tid < KH) bp[tid] = 0.f;
    __syncthreads();

    int lane = tid & 31, wid = tid >> 5;
    int l8 = lane & 7, g8 = lane >> 3;
    int warp0 = blockIdx.x * 8 + wid;
    int NW = gridDim.x * 8;

    float wr[8][4];
    #pragma unroll
    for (int j = 0; j < 8; j++)
        #pragma unroll
        for (int h = 0; h < 4; h++)
            wr[j][h] = Ws2[(l8 * 8 + j) * 4 + h];

    float s0 = 0.f, s1 = 0.f, s2 = 0.f, s3 = 0.f;
    int gmax = (E + 3) >> 2;

    int g = warp0;
    float4 cv0 = make_float4(0.f, 0.f, 0.f, 0.f), cv1 = cv0;
    if (g < gmax) {
        int e = g * 4 + g8;
        const float* ea = edge_attr + (size_t)(e < E ? e : 0) * KED + l8 * 8;
        cv0 = *(const float4*)ea;
        cv1 = *(const float4*)(ea + 4);
    }
    for (; g < gmax; ) {
        int gn = g + NW;
        float4 nv0, nv1;
        if (gn < gmax) {
            int en = gn * 4 + g8;
            const float* ea = edge_attr + (size_t)(en < E ? en : 0) * KED + l8 * 8;
            nv0 = *(const float4*)ea;
            nv1 = *(const float4*)(ea + 4);
        }
        int e = g * 4 + g8;
        bool valid = e < E;
        float av[8] = {cv0.x, cv0.y, cv0.z, cv0.w, cv1.x, cv1.y, cv1.z, cv1.w};
        float p0 = 0.f, p1 = 0.f, p2 = 0.f, p3 = 0.f;
        #pragma unroll
        for (int j = 0; j < 8; j++) {
            p0 += av[j] * wr[j][0];
            p1 += av[j] * wr[j][1];
            p2 += av[j] * wr[j][2];
            p3 += av[j] * wr[j][3];
        }
        #pragma unroll
        for (int m = 1; m <= 4; m <<= 1) {
            p0 += __shfl_xor_sync(FULLM, p0, m);
            p1 += __shfl_xor_sync(FULLM, p1, m);
            p2 += __shfl_xor_sync(FULLM, p2, m);
            p3 += __shfl_xor_sync(FULLM, p3, m);
        }
        if (l8 == 0 && valid) {
            int src = edge_index[e];
            int dst = edge_index[E + e];
            float4 as = g_asrc[src];
            int pos = atomicAdd(&g_cursor[dst], 1);
            g_ssrc[pos] = src;
            g_salpha[pos] = make_float4(as.x + p0, as.y + p1, as.z + p2, as.w + p3);
            s0 += p0; s1 += p1; s2 += p2; s3 += p3;
        }
        cv0 = nv0; cv1 = nv1;
        g = gn;
    }
    if (l8 == 0) {
        atomicAdd(&bp[0], s0);
        atomicAdd(&bp[1], s1);
        atomicAdd(&bp[2], s2);
        atomicAdd(&bp[3], s3);
    }
    __syncthreads();
    if (tid < KH) atomicAdd(&g_loopsum[tid], bp[tid]);
}

// ---------------- aggregation: warp per node, prefetched softmax + weighted sum ----------------
__global__ __launch_bounds__(256) void k_agg(const float* __restrict__ bias,
                                             float* __restrict__ out, int n, float invE) {
    int i = (blockIdx.x * blockDim.x + threadIdx.x) >> 5;
    int lane = threadIdx.x & 31;
    if (i >= n) return;

    int hl = lane >> 3;
    int sub = lane & 3;

    float adst_s = ((const float*)&g_adst[i])[sub];
    float asrc_s = ((const float*)&g_asrc[i])[sub];
    float lae_s  = g_loopsum[sub] * invE;
    float4 xpi = g_xproj[(size_t)i * 32 + lane];

    float4 acc = make_float4(0.f, 0.f, 0.f, 0.f);
    float dsum = 0.f;

    float vs = asrc_s + adst_s + lae_s;
    vs = vs > 0.f ? vs : 0.2f * vs;
    float ws = __expf(vs);
    if (lane < 4) dsum += ws;
    {
        float w = __shfl_sync(FULLM, ws, hl);
        acc.x += w * xpi.x; acc.y += w * xpi.y; acc.z += w * xpi.z; acc.w += w * xpi.w;
    }

    int beg = g_off[i], end = g_off[i + 1];
    const float* salpha_f = (const float*)g_salpha;

    // prefetch iteration 0
    float ca = 0.f; int cs = i;
    if (beg < end) {
        if (beg + (lane >> 2) < end) ca = salpha_f[(size_t)beg * 4 + lane];
        if (lane < 8 && beg + lane < end) cs = g_ssrc[beg + lane];
    }
    for (int base = beg; base < end; base += 8) {
        int nb = base + 8;
        float na = 0.f; int ns = i;
        if (nb < end) {
            if (nb + (lane >> 2) < end) na = salpha_f[(size_t)nb * 4 + lane];
            if (lane < 8 && nb + lane < end) ns = g_ssrc[nb + lane];
        }
        float w = 0.f;
        if (base + (lane >> 2) < end) {
            float a = ca + adst_s;
            a = a > 0.f ? a : 0.2f * a;
            w = __expf(a);
        }
        dsum += w;
        #pragma unroll
        for (int k = 0; k < 8; k++) {
            int s = __shfl_sync(FULLM, cs, k);
            float we = __shfl_sync(FULLM, w, k * 4 + hl);
            float4 xp = g_xproj[(size_t)s * 32 + lane];
            acc.x += we * xp.x; acc.y += we * xp.y;
            acc.z += we * xp.z; acc.w += we * xp.w;
        }
        ca = na; cs = ns;
    }
    #pragma unroll
    for (int m = 4; m <= 16; m <<= 1) dsum += __shfl_xor_sync(FULLM, dsum, m);
    float denom = __shfl_sync(FULLM, dsum, hl);
    float inv = 1.0f / denom;
    float4 b4 = *(const float4*)(bias + lane * 4);
    float4 o;
    o.x = acc.x * inv + b4.x;
    o.y = acc.y * inv + b4.y;
    o.z = acc.z * inv + b4.z;
    o.w = acc.w * inv + b4.w;
    *(float4*)(out + (size_t)i * KHC + lane * 4) = o;
}

// ---------------- launch (k_gemm at #4 for ncu capture) ----------------
extern "C" void kernel_launch(void* const* d_in, const int* in_sizes, int n_in,
                              void* d_out, int out_size) {
    const float* x         = (const float*)d_in[0];
    const int*   edge_idx  = (const int*)d_in[1];
    const float* edge_attr = (const float*)d_in[2];
    const float* W         = (const float*)d_in[3];
    const float* att_src   = (const float*)d_in[4];
    const float* att_dst   = (const float*)d_in[5];
    const float* W_edge    = (const float*)d_in[6];
    const float* att_edge  = (const float*)d_in[7];
    const float* bias      = (const float*)d_in[8];
    float* out = (float*)d_out;

    int n = in_sizes[0] / KIN;       // 100000
    int E = in_sizes[1] / 2;         // 1600000
    int nblk = (n + 255) / 256;      // 391

    k_reset<<<nblk, 256>>>(n);
    k_hist<<<(E + 255) / 256, 256>>>(edge_idx, E);
    k_w2<<<1, 256>>>(W_edge, att_edge);
    k_gemm<<<(n + 127) / 128, 256>>>(x, W, att_src, att_dst, n);  // #4 -> profiled
    k_scan1<<<nblk, 256>>>(n);
    k_scan2<<<1, 512>>>(nblk, n);
    k_scan3<<<nblk, 256>>>(n);
    k_scatf<<<2048, 256>>>(edge_idx, edge_attr, E);
    k_agg<<<(n + 7) / 8, 256>>>(bias, out, n, 1.0f / (float)E);
}